// round 6
// baseline (speedup 1.0000x reference)
#include <cuda_runtime.h>
#include <math.h>

// ---------------------------------------------------------------------------
// DilatedSparseRnnStack — R6: 1024 threads/CTA, 4-way K-split (8 warps/SMSP
// for latency hiding at unchanged L2 traffic), 2-rows-per-thread balanced
// reduction+epilogue, SMEM bias table, dynamic SMEM with 128KB reduction
// buffer aliased over the xh staging region.
// ---------------------------------------------------------------------------

namespace {
constexpr int T_STEPS = 256;
constexpr int BATCH   = 1024;
constexpr int IN_F    = 64;
constexpr int SSZ     = 256;
constexpr int HSZ     = 128;
constexpr int OSZ     = 128;
constexpr int OUT_F   = 8;
constexpr int RPC     = 8;
constexpr int NCTA    = BATCH / RPC;   // 128
constexpr int NTHR    = 1024;
constexpr int KTOT    = 320 + 384 + 448 + 384;  // 1536

// dynamic SMEM layout (bytes)
constexpr int SM_RED   = 0;            // 16*4*256*8 = 131072 (xh aliases first 28672)
constexpr int SM_OUT   = 131072;       // 4096
constexpr int SM_WOUT  = 135168;       // 4096
constexpr int SM_BIAS  = 139264;       // 16384 (4 layers x 256 j x float4)
constexpr int SM_TOTAL = 155648;
}

// Transposed, gate-interleaved weights: per layer [K][1024], fast index 4*j+g.
__device__ float g_WT[(size_t)KTOT * 1024];

// Circular dilation buffers. Slot offsets {0,1,4,10}, sizes {1,3,6,12}.
__device__ float4 g_bufH4[22u * BATCH * (HSZ / 4)];
__device__ float4 g_bufC4[22u * BATCH * (SSZ / 4)];

__device__ __forceinline__ float sigf(float v) {
    return 1.0f / (1.0f + __expf(-v));
}
__device__ __forceinline__ void ffma2(unsigned long long& d,
                                      unsigned long long a,
                                      unsigned long long b) {
    asm("fma.rn.f32x2 %0, %1, %2, %0;" : "+l"(d) : "l"(a), "l"(b));
}
__device__ __forceinline__ void fadd2(unsigned long long& d,
                                      unsigned long long a) {
    asm("add.rn.f32x2 %0, %0, %1;" : "+l"(d) : "l"(a));
}
__device__ __forceinline__ float2 u2f2(unsigned long long v) {
    float2 f;
    asm("mov.b64 {%0, %1}, %2;" : "=f"(f.x), "=f"(f.y) : "l"(v));
    return f;
}

// ---------------------------------------------------------------------------
// Prep: transpose + gate-interleave weights (read-coalesced over W).
// ---------------------------------------------------------------------------
__global__ void prep_kernel(const float* __restrict__ W0,
                            const float* __restrict__ W1,
                            const float* __restrict__ W2,
                            const float* __restrict__ W3)
{
    const int li = blockIdx.y;
    const float* W;
    int K, off;
    if (li == 0)      { W = W0; K = 320; off = 0; }
    else if (li == 1) { W = W1; K = 384; off = 320 * 1024; }
    else if (li == 2) { W = W2; K = 448; off = 704 * 1024; }
    else              { W = W3; K = 384; off = 1152 * 1024; }

    int idx = blockIdx.x * 256 + threadIdx.x;
    if (idx < 1024 * K) {
        int row = idx / K;           // g*256 + j
        int k   = idx - row * K;
        int g = row >> 8, j = row & 255;
        g_WT[(size_t)off + (size_t)k * 1024 + 4 * j + g] = W[idx];
    }
}

// ---------------------------------------------------------------------------
// One layer step. 1024 threads: qg = tid>>8 handles k-quarter qg and owns
// batch rows {2qg, 2qg+1} in the reduction/epilogue.
// ---------------------------------------------------------------------------
template <int K, int DIL, int LOFF, int LI, int WTOFF>
__device__ __forceinline__ void do_layer(
    int t, int tid, int row0,
    const float* __restrict__ xt,
    char* __restrict__ smem,
    float* __restrict__ s_out)   // [128 j][8 r]
{
    const int prevSlot = LOFF + (t - 1 + DIL) % DIL;
    const int curSlot  = LOFF + (t % DIL);
    const int qg = tid >> 8;
    const int j  = tid & 255;
    const int rb = 2 * qg;

    float2* s_xh2 = reinterpret_cast<float2*>(smem);
    unsigned long long* s_red = reinterpret_cast<unsigned long long*>(smem);

    __syncthreads();  // sync A: prev layer fully consumed

    // ---- build xh dup-pairs: s_xh2[k*8 + r] = {v, v} ----
    if (LI > 0) {
        float v = s_out[tid];       // out section at k-offset 0: identity map
        s_xh2[tid] = make_float2(v, v);
    }
    if (LI == 0 || LI == 2) {
        constexpr int XOFF = (LI == 0) ? 0 : OSZ;
        if (tid >= 512) {
            int tt = tid - 512;
            int r = tt >> 6, k = tt & 63;
            float v = xt[r * IN_F + k];
            s_xh2[(XOFF + k) * 8 + r] = make_float2(v, v);
        }
    }
    if (tid < 512) {
        constexpr int HOFF = (LI == 0) ? IN_F : (LI == 2) ? (OSZ + IN_F) : OSZ;
        int it = tid & 255;
        int r = it & 7, c = it >> 3;                 // c in 0..31
        float4 v;
        int b;
        if (qg == 0) {
            v = (t > 0)
                ? g_bufH4[((size_t)prevSlot * BATCH + row0 + r) * (HSZ / 4) + c]
                : make_float4(0.f, 0.f, 0.f, 0.f);
            b = (HOFF + 4 * c) * 8 + r;
        } else {
            if (t >= DIL) {
                v = g_bufH4[((size_t)curSlot * BATCH + row0 + r) * (HSZ / 4) + c];
            } else if (t > 0) {
                v = g_bufH4[((size_t)prevSlot * BATCH + row0 + r) * (HSZ / 4) + c];
            } else {
                v = make_float4(0.f, 0.f, 0.f, 0.f);
            }
            b = (HOFF + HSZ + 4 * c) * 8 + r;
        }
        s_xh2[b]      = make_float2(v.x, v.x);
        s_xh2[b + 8]  = make_float2(v.y, v.y);
        s_xh2[b + 16] = make_float2(v.z, v.z);
        s_xh2[b + 24] = make_float2(v.w, v.w);
    }

    __syncthreads();  // sync B: xh complete

    // ---- GEMM over this quarter's k-range ----
    unsigned long long acc[16];   // [0..7]=a01 rows, [8..15]=a23 rows
#pragma unroll
    for (int i = 0; i < 16; ++i) acc[i] = 0ull;

    {
        const char* wp = reinterpret_cast<const char*>(g_WT + WTOFF)
                       + (size_t)j * 16 + (size_t)qg * (K / 4) * 4096;
        const char* xp = smem + qg * (K / 4) * 64;
        for (int kb = 0; kb < K / 4; kb += 4) {
#pragma unroll
            for (int u = 0; u < 4; ++u) {
                ulonglong2 w = *reinterpret_cast<const ulonglong2*>(wp + u * 4096);
                {
                    ulonglong2 xA = *reinterpret_cast<const ulonglong2*>(xp + u * 64);
                    ffma2(acc[0], w.x, xA.x); ffma2(acc[8],  w.y, xA.x);
                    ffma2(acc[1], w.x, xA.y); ffma2(acc[9],  w.y, xA.y);
                }
                {
                    ulonglong2 xB = *reinterpret_cast<const ulonglong2*>(xp + u * 64 + 16);
                    ffma2(acc[2], w.x, xB.x); ffma2(acc[10], w.y, xB.x);
                    ffma2(acc[3], w.x, xB.y); ffma2(acc[11], w.y, xB.y);
                }
                {
                    ulonglong2 xC = *reinterpret_cast<const ulonglong2*>(xp + u * 64 + 32);
                    ffma2(acc[4], w.x, xC.x); ffma2(acc[12], w.y, xC.x);
                    ffma2(acc[5], w.x, xC.y); ffma2(acc[13], w.y, xC.y);
                }
                {
                    ulonglong2 xD = *reinterpret_cast<const ulonglong2*>(xp + u * 64 + 48);
                    ffma2(acc[6], w.x, xD.x); ffma2(acc[14], w.y, xD.x);
                    ffma2(acc[7], w.x, xD.y); ffma2(acc[15], w.y, xD.y);
                }
            }
            wp += 4 * 4096;
            xp += 4 * 64;
        }
    }

    // ---- C-state prefetch for owned rows (hidden under reduction) ----
    float* Cbase = reinterpret_cast<float*>(g_bufC4);
    float*       Ccur  = Cbase + ((size_t)curSlot  * BATCH + row0) * SSZ + j;
    const float* Cprev = Cbase + ((size_t)prevSlot * BATCH + row0) * SSZ + j;
    float pC0 = 0.f, pC1 = 0.f, dC0 = 0.f, dC1 = 0.f;
    if (t > 0) {
        pC0 = Cprev[(size_t)rb * SSZ];
        pC1 = Cprev[(size_t)(rb + 1) * SSZ];
    }
    if (t >= DIL) {
        dC0 = Ccur[(size_t)rb * SSZ];
        dC1 = Ccur[(size_t)(rb + 1) * SSZ];
    }

    __syncthreads();  // sync C: xh reads done; s_red usable

    // ---- write partials: buf[acc i][writer qg][j] ----
#pragma unroll
    for (int i = 0; i < 16; ++i) {
        s_red[(i * 4 + qg) * 256 + j] = acc[i];
    }

    __syncthreads();  // sync D: partials visible

    // ---- reduce owned rows (rb, rb+1) across the other 3 writers ----
#pragma unroll
    for (int w = 0; w < 4; ++w) {
        if (w != qg) {
            fadd2(acc[rb],         s_red[(rb * 4 + w) * 256 + j]);
            fadd2(acc[rb + 1],     s_red[((rb + 1) * 4 + w) * 256 + j]);
            fadd2(acc[8 + rb],     s_red[((8 + rb) * 4 + w) * 256 + j]);
            fadd2(acc[8 + rb + 1], s_red[((8 + rb + 1) * 4 + w) * 256 + j]);
        }
    }

    // ---- epilogue: 2 rows per thread, all 1024 threads ----
    const float4 bias =
        reinterpret_cast<const float4*>(smem + SM_BIAS)[LI * 256 + j];
    float* Hbase = reinterpret_cast<float*>(g_bufH4);
    float* Hcur  = Hbase + ((size_t)curSlot * BATCH + row0) * HSZ + (j - OSZ);

    float whole[2];
#pragma unroll
    for (int s = 0; s < 2; ++s) {
        const int row = rb + s;
        float2 G01 = u2f2(acc[row]);
        float2 G23 = u2f2(acc[8 + row]);
        float forget = sigf(G01.x + bias.x + 1.0f);
        float cand   = tanhf(G01.y + bias.y);
        float alpha  = sigf(G23.x + bias.z);
        float og     = sigf(G23.y + bias.w);
        float newC;
        if (t == 0) {
            newC = cand;
        } else {
            float pc = s ? pC1 : pC0;
            float wC = pc;
            if (t >= DIL) {
                float dc = s ? dC1 : dC0;
                wC = alpha * pc + (1.0f - alpha) * dc;
            }
            newC = forget * wC + (1.0f - forget) * cand;
        }
        Ccur[(size_t)row * SSZ] = newC;
        whole[s] = og * newC;
    }
    if (j < OSZ) {
        reinterpret_cast<float2*>(s_out)[j * 4 + qg] =
            make_float2(whole[0], whole[1]);
    } else {
        Hcur[(size_t)rb * HSZ]       = whole[0];
        Hcur[(size_t)(rb + 1) * HSZ] = whole[1];
    }
}

__global__ __launch_bounds__(NTHR, 1) void rnn_stack_kernel(
    const float* __restrict__ x,
    const float* __restrict__ b0, const float* __restrict__ b1,
    const float* __restrict__ b2, const float* __restrict__ b3,
    const float* __restrict__ Wout, const float* __restrict__ bout,
    float* __restrict__ out)
{
    extern __shared__ char smem[];
    float* s_out  = reinterpret_cast<float*>(smem + SM_OUT);
    float* s_wout = reinterpret_cast<float*>(smem + SM_WOUT);

    const int tid  = threadIdx.x;
    const int row0 = blockIdx.x * RPC;

    if (tid < 256) {
        reinterpret_cast<float4*>(s_wout)[tid] =
            reinterpret_cast<const float4*>(Wout)[tid];
    }
    {
        int li = tid >> 8, jj = tid & 255;
        const float* bp = (li == 0) ? b0 : (li == 1) ? b1 : (li == 2) ? b2 : b3;
        reinterpret_cast<float4*>(smem + SM_BIAS)[tid] =
            make_float4(bp[jj], bp[256 + jj], bp[512 + jj], bp[768 + jj]);
    }

    // projection mapping: seg = tid&15, o = (tid>>4)&7, r = tid>>7
    const int p_seg = tid & 15;
    const int p_o   = (tid >> 4) & 7;
    const int p_r   = tid >> 7;
    const float bo  = bout[p_o];

    for (int t = 0; t < T_STEPS; ++t) {
        const float* xt = x + ((size_t)t * BATCH + row0) * IN_F;

        do_layer<320,  1,  0, 0, 0>          (t, tid, row0, xt, smem, s_out);
        do_layer<384,  3,  1, 1, 320 * 1024> (t, tid, row0, xt, smem, s_out);
        do_layer<448,  6,  4, 2, 704 * 1024> (t, tid, row0, xt, smem, s_out);
        do_layer<384, 12, 10, 3, 1152 * 1024>(t, tid, row0, xt, smem, s_out);

        __syncthreads();  // layer-3 s_out ready

        // ---- output projection: all 1024 threads, width-16 shfl reduce ----
        {
            float acc = 0.f;
#pragma unroll
            for (int qq = 0; qq < 8; ++qq) {
                int q = qq * 16 + p_seg;
                acc = fmaf(s_out[q * 8 + p_r], s_wout[p_o * OSZ + q], acc);
            }
            acc += __shfl_down_sync(0xffffffffu, acc, 8, 16);
            acc += __shfl_down_sync(0xffffffffu, acc, 4, 16);
            acc += __shfl_down_sync(0xffffffffu, acc, 2, 16);
            acc += __shfl_down_sync(0xffffffffu, acc, 1, 16);
            if (p_seg == 0) {
                out[((size_t)t * BATCH + row0 + p_r) * OUT_F + p_o] = acc + bo;
            }
        }
        // next iteration's sync A protects s_out / smem reuse
    }
}

extern "C" void kernel_launch(void* const* d_in, const int* in_sizes, int n_in,
                              void* d_out, int out_size)
{
    (void)in_sizes; (void)n_in; (void)out_size;

    cudaFuncSetAttribute(rnn_stack_kernel,
                         cudaFuncAttributeMaxDynamicSharedMemorySize, SM_TOTAL);

    dim3 pgrid((1024 * 448 + 255) / 256, 4);
    prep_kernel<<<pgrid, 256>>>(
        (const float*)d_in[1], (const float*)d_in[3],
        (const float*)d_in[5], (const float*)d_in[7]);

    rnn_stack_kernel<<<NCTA, NTHR, SM_TOTAL>>>(
        (const float*)d_in[0],
        (const float*)d_in[2], (const float*)d_in[4],
        (const float*)d_in[6], (const float*)d_in[8],
        (const float*)d_in[9], (const float*)d_in[10],
        (float*)d_out);
}

// round 7
// speedup vs baseline: 1.4991x; 1.4991x over previous
#include <cuda_runtime.h>
#include <math.h>

// ---------------------------------------------------------------------------
// DilatedSparseRnnStack — R7: R5 skeleton (512 thr, 2-way K-split, pointer-
// walked GEMM, balanced reduction/epilogue) with ROW-PAIR accumulator packing:
// xh staged un-duplicated (halves LDS traffic vs R5); weights duplicated
// in-register via mov.b64 (alu pipe, which is idle).
// ---------------------------------------------------------------------------

namespace {
constexpr int T_STEPS = 256;
constexpr int BATCH   = 1024;
constexpr int IN_F    = 64;
constexpr int SSZ     = 256;
constexpr int HSZ     = 128;
constexpr int OSZ     = 128;
constexpr int OUT_F   = 8;
constexpr int RPC     = 8;
constexpr int NCTA    = BATCH / RPC;   // 128
constexpr int NTHR    = 512;
constexpr int KTOT    = 320 + 384 + 448 + 384;  // 1536
}

// Transposed, gate-interleaved weights: per layer [K][1024], fast index 4*j+g.
__device__ float g_WT[(size_t)KTOT * 1024];

// Circular dilation buffers. Slot offsets {0,1,4,10}, sizes {1,3,6,12}.
__device__ float4 g_bufH4[22u * BATCH * (HSZ / 4)];
__device__ float4 g_bufC4[22u * BATCH * (SSZ / 4)];

__device__ __forceinline__ float sigf(float v) {
    return 1.0f / (1.0f + __expf(-v));
}
__device__ __forceinline__ void ffma2(unsigned long long& d,
                                      unsigned long long a,
                                      unsigned long long b) {
    asm("fma.rn.f32x2 %0, %1, %2, %0;" : "+l"(d) : "l"(a), "l"(b));
}
__device__ __forceinline__ void fadd2(unsigned long long& d,
                                      unsigned long long a) {
    asm("add.rn.f32x2 %0, %0, %1;" : "+l"(d) : "l"(a));
}
__device__ __forceinline__ unsigned long long dup2(float w) {
    unsigned long long r;
    asm("mov.b64 %0, {%1, %1};" : "=l"(r) : "f"(w));
    return r;
}
__device__ __forceinline__ float2 u2f2(unsigned long long v) {
    float2 f;
    asm("mov.b64 {%0, %1}, %2;" : "=f"(f.x), "=f"(f.y) : "l"(v));
    return f;
}

// ---------------------------------------------------------------------------
// Prep: transpose + gate-interleave weights (read-coalesced over W).
// ---------------------------------------------------------------------------
__global__ void prep_kernel(const float* __restrict__ W0,
                            const float* __restrict__ W1,
                            const float* __restrict__ W2,
                            const float* __restrict__ W3)
{
    const int li = blockIdx.y;
    const float* W;
    int K, off;
    if (li == 0)      { W = W0; K = 320; off = 0; }
    else if (li == 1) { W = W1; K = 384; off = 320 * 1024; }
    else if (li == 2) { W = W2; K = 448; off = 704 * 1024; }
    else              { W = W3; K = 384; off = 1152 * 1024; }

    int idx = blockIdx.x * 256 + threadIdx.x;
    if (idx < 1024 * K) {
        int row = idx / K;           // g*256 + j
        int k   = idx - row * K;
        int g = row >> 8, j = row & 255;
        g_WT[(size_t)off + (size_t)k * 1024 + 4 * j + g] = W[idx];
    }
}

// ---------------------------------------------------------------------------
// One layer step. 512 threads: half = tid>>8 handles k-range half and owns
// batch rows rb..rb+3 (rb = 4*half) in the epilogue.
// s_big (32KB): xh floats [k*8+r] (14KB) during GEMM; reduction buf after.
// ---------------------------------------------------------------------------
template <int K, int DIL, int LOFF, int LI, int WTOFF>
__device__ __forceinline__ void do_layer(
    int t, int tid, int row0,
    const float* __restrict__ xt,
    float4 bias,
    unsigned long long* __restrict__ s_big,
    float* __restrict__ s_out)   // [128 j][8 r]
{
    const int prevSlot = LOFF + (t - 1 + DIL) % DIL;
    const int curSlot  = LOFF + (t % DIL);
    const int half = tid >> 8;
    const int j    = tid & 255;
    const int rb   = half * 4;           // rows this thread epilogues

    float* s_xhf = reinterpret_cast<float*>(s_big);

    __syncthreads();  // sync A: prev layer fully consumed

    // ---- C-state prefetch for owned rows (hidden under GEMM) ----
    float* Cbase = reinterpret_cast<float*>(g_bufC4);
    float*       Ccur  = Cbase + ((size_t)curSlot  * BATCH + row0) * SSZ + j;
    const float* Cprev = Cbase + ((size_t)prevSlot * BATCH + row0) * SSZ + j;
    float pC[4]  = {0.f, 0.f, 0.f, 0.f};
    float dCv[4] = {0.f, 0.f, 0.f, 0.f};
    if (t > 0) {
#pragma unroll
        for (int r = 0; r < 4; ++r) pC[r] = Cprev[(size_t)(rb + r) * SSZ];
    }
    if (t >= DIL) {
#pragma unroll
        for (int r = 0; r < 4; ++r) dCv[r] = Ccur[(size_t)(rb + r) * SSZ];
    }

    // ---- build xh in SMEM (un-duplicated): s_xhf[k*8 + r] ----
    if (LI > 0) {
        // out section at k-offset 0: s_out[j*8+r] -> identity index mapping
        s_xhf[tid]       = s_out[tid];
        s_xhf[tid + 512] = s_out[tid + 512];
    }
    if (LI == 0 || LI == 2) {
        constexpr int XOFF = (LI == 0) ? 0 : OSZ;
        if (tid < 128) {
            int r = tid & 7, k4 = tid >> 3;          // k4 in 0..15
            const float4 v = reinterpret_cast<const float4*>(xt)[r * (IN_F / 4) + k4];
            int b = (XOFF + 4 * k4) * 8 + r;
            s_xhf[b]      = v.x;
            s_xhf[b + 8]  = v.y;
            s_xhf[b + 16] = v.z;
            s_xhf[b + 24] = v.w;
        }
    }
    {
        constexpr int HOFF = (LI == 0) ? IN_F : (LI == 2) ? (OSZ + IN_F) : OSZ;
        int r = j & 7, c = j >> 3;                   // c in 0..31
        float4 v;
        int b;
        if (half == 0) {
            v = (t > 0)
                ? g_bufH4[((size_t)prevSlot * BATCH + row0 + r) * (HSZ / 4) + c]
                : make_float4(0.f, 0.f, 0.f, 0.f);
            b = (HOFF + 4 * c) * 8 + r;
        } else {
            if (t >= DIL) {
                v = g_bufH4[((size_t)curSlot * BATCH + row0 + r) * (HSZ / 4) + c];
            } else if (t > 0) {
                v = g_bufH4[((size_t)prevSlot * BATCH + row0 + r) * (HSZ / 4) + c];
            } else {
                v = make_float4(0.f, 0.f, 0.f, 0.f);
            }
            b = (HOFF + HSZ + 4 * c) * 8 + r;
        }
        s_xhf[b]      = v.x;
        s_xhf[b + 8]  = v.y;
        s_xhf[b + 16] = v.z;
        s_xhf[b + 24] = v.w;
    }

    __syncthreads();  // sync B: xh complete

    // ---- GEMM over this half's k-range (row-pair packing) ----
    // acc[g][p] accumulates rows {2p, 2p+1} for gate g of column j.
    unsigned long long aG0[4], aG1[4], aG2[4], aG3[4];
#pragma unroll
    for (int p = 0; p < 4; ++p) { aG0[p] = aG1[p] = aG2[p] = aG3[p] = 0ull; }

    {
        const char* wp = reinterpret_cast<const char*>(g_WT + WTOFF)
                       + (size_t)j * 16 + (size_t)half * (K / 2) * 4096;
        const char* xp = reinterpret_cast<const char*>(s_big)
                       + half * (K / 2) * 32;
        for (int kb = 0; kb < K / 2; kb += 8) {
#pragma unroll
            for (int u = 0; u < 8; ++u) {
                float4 w = *reinterpret_cast<const float4*>(wp + u * 4096);
                ulonglong2 xA = *reinterpret_cast<const ulonglong2*>(xp + u * 32);
                ulonglong2 xB = *reinterpret_cast<const ulonglong2*>(xp + u * 32 + 16);
                unsigned long long w0 = dup2(w.x);
                unsigned long long w1 = dup2(w.y);
                unsigned long long w2 = dup2(w.z);
                unsigned long long w3 = dup2(w.w);
                ffma2(aG0[0], w0, xA.x); ffma2(aG0[1], w0, xA.y);
                ffma2(aG0[2], w0, xB.x); ffma2(aG0[3], w0, xB.y);
                ffma2(aG1[0], w1, xA.x); ffma2(aG1[1], w1, xA.y);
                ffma2(aG1[2], w1, xB.x); ffma2(aG1[3], w1, xB.y);
                ffma2(aG2[0], w2, xA.x); ffma2(aG2[1], w2, xA.y);
                ffma2(aG2[2], w2, xB.x); ffma2(aG2[3], w2, xB.y);
                ffma2(aG3[0], w3, xA.x); ffma2(aG3[1], w3, xA.y);
                ffma2(aG3[2], w3, xB.x); ffma2(aG3[3], w3, xB.y);
            }
            wp += 8 * 4096;
            xp += 8 * 32;
        }
    }

    __syncthreads();  // sync C: xh reads done; s_big becomes reduction buffer

    // ---- balanced exchange: write partials for NON-owned row-pairs ----
    // pairs {0,1} owned by half0, {2,3} by half1. Slot id = (g*4+p)*256+j.
    {
        const int po = 2 - 2 * half;   // other half's first pair
#pragma unroll
        for (int i = 0; i < 2; ++i) {
            s_big[((0 * 4) + po + i) * 256 + j] = aG0[po + i];
            s_big[((1 * 4) + po + i) * 256 + j] = aG1[po + i];
            s_big[((2 * 4) + po + i) * 256 + j] = aG2[po + i];
            s_big[((3 * 4) + po + i) * 256 + j] = aG3[po + i];
        }
    }

    __syncthreads();  // sync D: partials visible

    {
        const int pm = 2 * half;       // my first pair
#pragma unroll
        for (int i = 0; i < 2; ++i) {
            fadd2(aG0[pm + i], s_big[((0 * 4) + pm + i) * 256 + j]);
            fadd2(aG1[pm + i], s_big[((1 * 4) + pm + i) * 256 + j]);
            fadd2(aG2[pm + i], s_big[((2 * 4) + pm + i) * 256 + j]);
            fadd2(aG3[pm + i], s_big[((3 * 4) + pm + i) * 256 + j]);
        }
    }

    // ---- epilogue: 4 rows (2 owned pairs) per thread ----
    float* Hbase = reinterpret_cast<float*>(g_bufH4);
    float* Hcur  = Hbase + ((size_t)curSlot * BATCH + row0) * HSZ + (j - OSZ);

    float whole[4];
#pragma unroll
    for (int i = 0; i < 2; ++i) {
        const int p = 2 * half + i;
        float2 G0 = u2f2(aG0[p]);
        float2 G1 = u2f2(aG1[p]);
        float2 G2 = u2f2(aG2[p]);
        float2 G3 = u2f2(aG3[p]);
#pragma unroll
        for (int s = 0; s < 2; ++s) {
            const int r = 2 * i + s;            // 0..3 within owned block
            const int row = rb + r;
            float forget = sigf((s ? G0.y : G0.x) + bias.x + 1.0f);
            float cand   = tanhf((s ? G1.y : G1.x) + bias.y);
            float alpha  = sigf((s ? G2.y : G2.x) + bias.z);
            float og     = sigf((s ? G3.y : G3.x) + bias.w);
            float newC;
            if (t == 0) {
                newC = cand;
            } else {
                float wC = pC[r];
                if (t >= DIL) {
                    wC = alpha * pC[r] + (1.0f - alpha) * dCv[r];
                }
                newC = forget * wC + (1.0f - forget) * cand;
            }
            Ccur[(size_t)row * SSZ] = newC;
            whole[r] = og * newC;
        }
    }
    if (j < OSZ) {
        reinterpret_cast<float4*>(s_out)[j * 2 + half] =
            make_float4(whole[0], whole[1], whole[2], whole[3]);
    } else {
#pragma unroll
        for (int r = 0; r < 4; ++r) {
            Hcur[(size_t)(rb + r) * HSZ] = whole[r];
        }
    }
}

__global__ __launch_bounds__(NTHR, 1) void rnn_stack_kernel(
    const float* __restrict__ x,
    const float* __restrict__ b0, const float* __restrict__ b1,
    const float* __restrict__ b2, const float* __restrict__ b3,
    const float* __restrict__ Wout, const float* __restrict__ bout,
    float* __restrict__ out)
{
    __shared__ __align__(16) unsigned long long s_big[4096];  // 32 KB
    __shared__ __align__(16) float s_out[1024];               //  4 KB
    __shared__ __align__(16) float s_wout[OUT_F * OSZ];       //  4 KB

    const int tid  = threadIdx.x;
    const int row0 = blockIdx.x * RPC;
    const int j    = tid & 255;

    if (tid < 256) {
        reinterpret_cast<float4*>(s_wout)[tid] =
            reinterpret_cast<const float4*>(Wout)[tid];
    }
    float4 bs0 = make_float4(b0[j], b0[256 + j], b0[512 + j], b0[768 + j]);
    float4 bs1 = make_float4(b1[j], b1[256 + j], b1[512 + j], b1[768 + j]);
    float4 bs2 = make_float4(b2[j], b2[256 + j], b2[512 + j], b2[768 + j]);
    float4 bs3 = make_float4(b3[j], b3[256 + j], b3[512 + j], b3[768 + j]);

    // projection mapping: seg = tid&7 (k-segment), o = (tid>>3)&7, r = tid>>6
    const int p_seg = tid & 7;
    const int p_o   = (tid >> 3) & 7;
    const int p_r   = tid >> 6;
    const float bo  = bout[p_o];

    for (int t = 0; t < T_STEPS; ++t) {
        const float* xt = x + ((size_t)t * BATCH + row0) * IN_F;

        do_layer<320,  1,  0, 0, 0>          (t, tid, row0, xt, bs0, s_big, s_out);
        do_layer<384,  3,  1, 1, 320 * 1024> (t, tid, row0, xt, bs1, s_big, s_out);
        do_layer<448,  6,  4, 2, 704 * 1024> (t, tid, row0, xt, bs2, s_big, s_out);
        do_layer<384, 12, 10, 3, 1152 * 1024>(t, tid, row0, xt, bs3, s_big, s_out);

        __syncthreads();  // layer-3 s_out ready

        // ---- output projection: all 512 threads, shfl octet reduction ----
        {
            float acc = 0.f;
#pragma unroll
            for (int qq = 0; qq < 16; ++qq) {
                int q = qq * 8 + p_seg;
                acc = fmaf(s_out[q * 8 + p_r], s_wout[p_o * OSZ + q], acc);
            }
            acc += __shfl_down_sync(0xffffffffu, acc, 4, 8);
            acc += __shfl_down_sync(0xffffffffu, acc, 2, 8);
            acc += __shfl_down_sync(0xffffffffu, acc, 1, 8);
            if (p_seg == 0) {
                out[((size_t)t * BATCH + row0 + p_r) * OUT_F + p_o] = acc + bo;
            }
        }
        // next iteration's sync A protects s_out / s_big reuse
    }
}

extern "C" void kernel_launch(void* const* d_in, const int* in_sizes, int n_in,
                              void* d_out, int out_size)
{
    (void)in_sizes; (void)n_in; (void)out_size;

    dim3 pgrid((1024 * 448 + 255) / 256, 4);
    prep_kernel<<<pgrid, 256>>>(
        (const float*)d_in[1], (const float*)d_in[3],
        (const float*)d_in[5], (const float*)d_in[7]);

    rnn_stack_kernel<<<NCTA, NTHR>>>(
        (const float*)d_in[0],
        (const float*)d_in[2], (const float*)d_in[4],
        (const float*)d_in[6], (const float*)d_in[8],
        (const float*)d_in[9], (const float*)d_in[10],
        (float*)d_out);
}

// round 8
// speedup vs baseline: 1.5193x; 1.0135x over previous
#include <cuda_runtime.h>
#include <math.h>

// ---------------------------------------------------------------------------
// DilatedSparseRnnStack — R8: R7 + state buffers relaid as [slot][group][j][r]
// so all C/H accesses are coalesced float4 (was: stride-1KB scalar scatter,
// ~40k L1 wavefronts/step -> ~1k). Separate reduction buffer deletes sync C.
// ---------------------------------------------------------------------------

namespace {
constexpr int T_STEPS = 256;
constexpr int BATCH   = 1024;
constexpr int IN_F    = 64;
constexpr int SSZ     = 256;
constexpr int HSZ     = 128;
constexpr int OSZ     = 128;
constexpr int OUT_F   = 8;
constexpr int RPC     = 8;
constexpr int NCTA    = BATCH / RPC;   // 128
constexpr int NTHR    = 512;
constexpr int KTOT    = 320 + 384 + 448 + 384;  // 1536

// dynamic SMEM layout (bytes)
constexpr int SM_XH    = 0;        // 448*8*4 = 14336
constexpr int SM_RED   = 14336;    // 16*256*8 = 32768
constexpr int SM_OUT   = 47104;    // 4096
constexpr int SM_WOUT  = 51200;    // 4096
constexpr int SM_TOTAL = 55296;
}

// Transposed, gate-interleaved weights: per layer [K][1024], fast index 4*j+g.
__device__ float g_WT[(size_t)KTOT * 1024];

// Circular dilation buffers, CTA-local layout:
//   C: [slot 22][group 128][j 256][r 8]  (float4 index = ((slot*128+g)*256+j)*2 + r/4)
//   H: [slot 22][group 128][jh 128][r 8]
__device__ float4 g_bufC4[22u * 128 * 256 * 2];
__device__ float4 g_bufH4[22u * 128 * 128 * 2];

__device__ __forceinline__ float sigf(float v) {
    return 1.0f / (1.0f + __expf(-v));
}
__device__ __forceinline__ void ffma2(unsigned long long& d,
                                      unsigned long long a,
                                      unsigned long long b) {
    asm("fma.rn.f32x2 %0, %1, %2, %0;" : "+l"(d) : "l"(a), "l"(b));
}
__device__ __forceinline__ void fadd2(unsigned long long& d,
                                      unsigned long long a) {
    asm("add.rn.f32x2 %0, %0, %1;" : "+l"(d) : "l"(a));
}
__device__ __forceinline__ unsigned long long dup2(float w) {
    unsigned long long r;
    asm("mov.b64 %0, {%1, %1};" : "=l"(r) : "f"(w));
    return r;
}
__device__ __forceinline__ float2 u2f2(unsigned long long v) {
    float2 f;
    asm("mov.b64 {%0, %1}, %2;" : "=f"(f.x), "=f"(f.y) : "l"(v));
    return f;
}

// ---------------------------------------------------------------------------
// Prep: transpose + gate-interleave weights (read-coalesced over W).
// ---------------------------------------------------------------------------
__global__ void prep_kernel(const float* __restrict__ W0,
                            const float* __restrict__ W1,
                            const float* __restrict__ W2,
                            const float* __restrict__ W3)
{
    const int li = blockIdx.y;
    const float* W;
    int K, off;
    if (li == 0)      { W = W0; K = 320; off = 0; }
    else if (li == 1) { W = W1; K = 384; off = 320 * 1024; }
    else if (li == 2) { W = W2; K = 448; off = 704 * 1024; }
    else              { W = W3; K = 384; off = 1152 * 1024; }

    int idx = blockIdx.x * 256 + threadIdx.x;
    if (idx < 1024 * K) {
        int row = idx / K;           // g*256 + j
        int k   = idx - row * K;
        int g = row >> 8, j = row & 255;
        g_WT[(size_t)off + (size_t)k * 1024 + 4 * j + g] = W[idx];
    }
}

// ---------------------------------------------------------------------------
// One layer step. 512 threads: half = tid>>8 handles k-range half and owns
// batch rows rb..rb+3 (rb = 4*half) in the epilogue.
// ---------------------------------------------------------------------------
template <int K, int DIL, int LOFF, int LI, int WTOFF>
__device__ __forceinline__ void do_layer(
    int t, int tid, int group,
    const float* __restrict__ xt,
    float4 bias,
    char* __restrict__ smem)
{
    const int prevSlot = LOFF + (t - 1 + DIL) % DIL;
    const int curSlot  = LOFF + (t % DIL);
    const int half = tid >> 8;
    const int j    = tid & 255;

    float* s_xhf = reinterpret_cast<float*>(smem + SM_XH);
    unsigned long long* s_red =
        reinterpret_cast<unsigned long long*>(smem + SM_RED);
    float* s_out = reinterpret_cast<float*>(smem + SM_OUT);

    __syncthreads();  // sync A: prev layer (incl. its s_red reads) done

    // ---- C-state prefetch: coalesced float4 of the 4 owned rows ----
    const size_t cidx = ((size_t)(curSlot  * 128 + group) * 256 + j) * 2 + half;
    const size_t pidx = ((size_t)(prevSlot * 128 + group) * 256 + j) * 2 + half;
    float4 pC4 = make_float4(0.f, 0.f, 0.f, 0.f);
    float4 dC4 = make_float4(0.f, 0.f, 0.f, 0.f);
    if (t > 0)    pC4 = g_bufC4[pidx];
    if (t >= DIL) dC4 = g_bufC4[cidx];

    // ---- build xh in SMEM: s_xhf[k*8 + r] ----
    if (LI > 0) {
        // out section at k-offset 0: s_out[j*8+r] -> identity index mapping
        s_xhf[tid]       = s_out[tid];
        s_xhf[tid + 512] = s_out[tid + 512];
    }
    if (LI == 0 || LI == 2) {
        constexpr int XOFF = (LI == 0) ? 0 : OSZ;
        if (tid < 128) {
            int r = tid & 7, k4 = tid >> 3;          // k4 in 0..15
            const float4 v = reinterpret_cast<const float4*>(xt)[r * (IN_F / 4) + k4];
            int b = (XOFF + 4 * k4) * 8 + r;
            s_xhf[b]      = v.x;
            s_xhf[b + 8]  = v.y;
            s_xhf[b + 16] = v.z;
            s_xhf[b + 24] = v.w;
        }
    }
    {
        // prevH (half 0) / dH (half 1): fully coalesced LDG.128 -> STS.128
        constexpr int HOFF = (LI == 0) ? IN_F : (LI == 2) ? (OSZ + IN_F) : OSZ;
        const int slotH = (half == 0) ? prevSlot
                                      : ((t >= DIL) ? curSlot : prevSlot);
        float4 v = make_float4(0.f, 0.f, 0.f, 0.f);
        if (t > 0) {
            v = g_bufH4[((size_t)(slotH * 128 + group) * 128) * 2 + j];
        }
        const int jh = j >> 1, r0 = (j & 1) * 4;
        const int dst = (HOFF + half * HSZ + jh) * 8 + r0;
        *reinterpret_cast<float4*>(&s_xhf[dst]) = v;
    }

    __syncthreads();  // sync B: xh complete

    // ---- GEMM over this half's k-range (row-pair packing) ----
    unsigned long long aG0[4], aG1[4], aG2[4], aG3[4];
#pragma unroll
    for (int p = 0; p < 4; ++p) { aG0[p] = aG1[p] = aG2[p] = aG3[p] = 0ull; }

    {
        const char* wp = reinterpret_cast<const char*>(g_WT + WTOFF)
                       + (size_t)j * 16 + (size_t)half * (K / 2) * 4096;
        const char* xp = smem + SM_XH + half * (K / 2) * 32;
        for (int kb = 0; kb < K / 2; kb += 8) {
#pragma unroll
            for (int u = 0; u < 8; ++u) {
                float4 w = *reinterpret_cast<const float4*>(wp + u * 4096);
                ulonglong2 xA = *reinterpret_cast<const ulonglong2*>(xp + u * 32);
                ulonglong2 xB = *reinterpret_cast<const ulonglong2*>(xp + u * 32 + 16);
                unsigned long long w0 = dup2(w.x);
                unsigned long long w1 = dup2(w.y);
                unsigned long long w2 = dup2(w.z);
                unsigned long long w3 = dup2(w.w);
                ffma2(aG0[0], w0, xA.x); ffma2(aG0[1], w0, xA.y);
                ffma2(aG0[2], w0, xB.x); ffma2(aG0[3], w0, xB.y);
                ffma2(aG1[0], w1, xA.x); ffma2(aG1[1], w1, xA.y);
                ffma2(aG1[2], w1, xB.x); ffma2(aG1[3], w1, xB.y);
                ffma2(aG2[0], w2, xA.x); ffma2(aG2[1], w2, xA.y);
                ffma2(aG2[2], w2, xB.x); ffma2(aG2[3], w2, xB.y);
                ffma2(aG3[0], w3, xA.x); ffma2(aG3[1], w3, xA.y);
                ffma2(aG3[2], w3, xB.x); ffma2(aG3[3], w3, xB.y);
            }
            wp += 8 * 4096;
            xp += 8 * 32;
        }
    }

    // ---- write partials for NON-owned row-pairs (separate buffer: no sync
    //      needed before the writes; prev layer's reads fenced by sync A) ----
    {
        const int po = 2 - 2 * half;   // other half's first pair
#pragma unroll
        for (int i = 0; i < 2; ++i) {
            s_red[((0 * 4) + po + i) * 256 + j] = aG0[po + i];
            s_red[((1 * 4) + po + i) * 256 + j] = aG1[po + i];
            s_red[((2 * 4) + po + i) * 256 + j] = aG2[po + i];
            s_red[((3 * 4) + po + i) * 256 + j] = aG3[po + i];
        }
    }

    __syncthreads();  // sync D: partials visible

    {
        const int pm = 2 * half;       // my first pair
#pragma unroll
        for (int i = 0; i < 2; ++i) {
            fadd2(aG0[pm + i], s_red[((0 * 4) + pm + i) * 256 + j]);
            fadd2(aG1[pm + i], s_red[((1 * 4) + pm + i) * 256 + j]);
            fadd2(aG2[pm + i], s_red[((2 * 4) + pm + i) * 256 + j]);
            fadd2(aG3[pm + i], s_red[((3 * 4) + pm + i) * 256 + j]);
        }
    }

    // ---- epilogue: 4 owned rows, all float4 state I/O ----
    float nC[4], wh[4];
#pragma unroll
    for (int i = 0; i < 2; ++i) {
        const int p = 2 * half + i;
        float2 G0 = u2f2(aG0[p]);
        float2 G1 = u2f2(aG1[p]);
        float2 G2 = u2f2(aG2[p]);
        float2 G3 = u2f2(aG3[p]);
#pragma unroll
        for (int s = 0; s < 2; ++s) {
            const int r = 2 * i + s;            // 0..3 within owned block
            float forget = sigf((s ? G0.y : G0.x) + bias.x + 1.0f);
            float cand   = tanhf((s ? G1.y : G1.x) + bias.y);
            float alpha  = sigf((s ? G2.y : G2.x) + bias.z);
            float og     = sigf((s ? G3.y : G3.x) + bias.w);
            float pc = (r == 0) ? pC4.x : (r == 1) ? pC4.y : (r == 2) ? pC4.z : pC4.w;
            float dc = (r == 0) ? dC4.x : (r == 1) ? dC4.y : (r == 2) ? dC4.z : dC4.w;
            float newC;
            if (t == 0) {
                newC = cand;
            } else {
                float wC = pc;
                if (t >= DIL) {
                    wC = alpha * pc + (1.0f - alpha) * dc;
                }
                newC = forget * wC + (1.0f - forget) * cand;
            }
            nC[r] = newC;
            wh[r] = og * newC;
        }
    }
    g_bufC4[cidx] = make_float4(nC[0], nC[1], nC[2], nC[3]);
    if (j < OSZ) {
        reinterpret_cast<float4*>(s_out)[j * 2 + half] =
            make_float4(wh[0], wh[1], wh[2], wh[3]);
    } else {
        g_bufH4[((size_t)(curSlot * 128 + group) * 128 + (j - OSZ)) * 2 + half] =
            make_float4(wh[0], wh[1], wh[2], wh[3]);
    }
}

__global__ __launch_bounds__(NTHR, 1) void rnn_stack_kernel(
    const float* __restrict__ x,
    const float* __restrict__ b0, const float* __restrict__ b1,
    const float* __restrict__ b2, const float* __restrict__ b3,
    const float* __restrict__ Wout, const float* __restrict__ bout,
    float* __restrict__ out)
{
    extern __shared__ char smem[];
    float* s_out  = reinterpret_cast<float*>(smem + SM_OUT);
    float* s_wout = reinterpret_cast<float*>(smem + SM_WOUT);

    const int tid   = threadIdx.x;
    const int group = blockIdx.x;
    const int row0  = group * RPC;
    const int j     = tid & 255;

    if (tid < 256) {
        reinterpret_cast<float4*>(s_wout)[tid] =
            reinterpret_cast<const float4*>(Wout)[tid];
    }
    float4 bs0 = make_float4(b0[j], b0[256 + j], b0[512 + j], b0[768 + j]);
    float4 bs1 = make_float4(b1[j], b1[256 + j], b1[512 + j], b1[768 + j]);
    float4 bs2 = make_float4(b2[j], b2[256 + j], b2[512 + j], b2[768 + j]);
    float4 bs3 = make_float4(b3[j], b3[256 + j], b3[512 + j], b3[768 + j]);

    // projection mapping: seg = tid&7 (k-segment), o = (tid>>3)&7, r = tid>>6
    const int p_seg = tid & 7;
    const int p_o   = (tid >> 3) & 7;
    const int p_r   = tid >> 6;
    const float bo  = bout[p_o];

    for (int t = 0; t < T_STEPS; ++t) {
        const float* xt = x + ((size_t)t * BATCH + row0) * IN_F;

        do_layer<320,  1,  0, 0, 0>          (t, tid, group, xt, bs0, smem);
        do_layer<384,  3,  1, 1, 320 * 1024> (t, tid, group, xt, bs1, smem);
        do_layer<448,  6,  4, 2, 704 * 1024> (t, tid, group, xt, bs2, smem);
        do_layer<384, 12, 10, 3, 1152 * 1024>(t, tid, group, xt, bs3, smem);

        __syncthreads();  // layer-3 s_out ready

        // ---- output projection: all 512 threads, shfl octet reduction ----
        {
            float acc = 0.f;
#pragma unroll
            for (int qq = 0; qq < 16; ++qq) {
                int q = qq * 8 + p_seg;
                acc = fmaf(s_out[q * 8 + p_r], s_wout[p_o * OSZ + q], acc);
            }
            acc += __shfl_down_sync(0xffffffffu, acc, 4, 8);
            acc += __shfl_down_sync(0xffffffffu, acc, 2, 8);
            acc += __shfl_down_sync(0xffffffffu, acc, 1, 8);
            if (p_seg == 0) {
                out[((size_t)t * BATCH + row0 + p_r) * OUT_F + p_o] = acc + bo;
            }
        }
        // next iteration's sync A protects s_out / smem reuse
    }
}

extern "C" void kernel_launch(void* const* d_in, const int* in_sizes, int n_in,
                              void* d_out, int out_size)
{
    (void)in_sizes; (void)n_in; (void)out_size;

    cudaFuncSetAttribute(rnn_stack_kernel,
                         cudaFuncAttributeMaxDynamicSharedMemorySize, SM_TOTAL);

    dim3 pgrid((1024 * 448 + 255) / 256, 4);
    prep_kernel<<<pgrid, 256>>>(
        (const float*)d_in[1], (const float*)d_in[3],
        (const float*)d_in[5], (const float*)d_in[7]);

    rnn_stack_kernel<<<NCTA, NTHR, SM_TOTAL>>>(
        (const float*)d_in[0],
        (const float*)d_in[2], (const float*)d_in[4],
        (const float*)d_in[6], (const float*)d_in[8],
        (const float*)d_in[9], (const float*)d_in[10],
        (float*)d_out);
}